// round 3
// baseline (speedup 1.0000x reference)
#include <cuda_runtime.h>
#include <stdint.h>
#include <math.h>

#define Bv 16
#define Hv 512
#define Wv 512
#define Cv 3
#define TOT (Bv*Hv*Wv*Cv)   // 12,582,912

// Scratch (device globals -- no runtime allocation allowed)
__device__ float   g_blur[TOT];
__device__ uint8_t g_state[TOT];   // planar [b*3+c][y][x]: 0 none, 1 weak, 2 edge
__device__ unsigned g_gen;
__device__ unsigned g_cnt;
__device__ int      g_changed;

// ---------------- error-free compensated summation (pure f32, exact products)
__device__ __forceinline__ void two_sum(float a, float b, float& s, float& e) {
    s = __fadd_rn(a, b);
    float bb = __fsub_rn(s, a);
    e = __fadd_rn(__fsub_rn(a, __fsub_rn(s, bb)), __fsub_rn(b, bb));
}

template <int N>
__device__ __forceinline__ float sum_exact(const float* t) {
    float s = t[0], e = 0.f;
#pragma unroll
    for (int i = 1; i < N; ++i) {
        float ei;
        two_sum(s, t[i], s, ei);
        e = __fadd_rn(e, ei);
    }
    return __fadd_rn(s, e);   // correctly-rounded sum (ORO Sum2)
}

// ---------------------------------------------------------------- K1: blur
// Products with power-of-two weights are exact; compensated sum gives the
// correctly-rounded (order-independent) result.
__global__ void blur_k(const float* __restrict__ x) {
    int n = blockIdx.x * 256 + threadIdx.x;
    if (n == 0) { g_gen = 0; g_cnt = 0; g_changed = 0; }   // reset barrier state each replay
    if (n >= TOT) return;
    int c  = n % 3;
    int xx = (n / 3) % Wv;
    int yy = (n / (3 * Wv)) % Hv;
    int b  = n / (3 * Wv * Hv);
    const float* base = x + (size_t)b * Hv * Wv * 3;
    float t[9];
    int k = 0;
#pragma unroll
    for (int dy = -1; dy <= 1; ++dy) {
        int y2 = yy + dy;
        bool yok = (unsigned)y2 < (unsigned)Hv;
#pragma unroll
        for (int dx = -1; dx <= 1; ++dx) {
            int x2 = xx + dx;
            bool ok = yok && ((unsigned)x2 < (unsigned)Wv);
            float v = ok ? __ldg(base + (y2 * Wv + x2) * 3 + c) : 0.f;
            float w = (dy == 0) ? ((dx == 0) ? 0.25f : 0.125f)
                                : ((dx == 0) ? 0.125f : 0.0625f);
            t[k++] = __fmul_rn(v, w);   // exact (power-of-two weight)
        }
    }
    g_blur[n] = sum_exact<9>(t);
}

// ------------------------------------------- K2: sobel + mag + NMS + threshold
#define TY 16
#define TX 32
#define SBW 108   // (32+4)*3
#define SMW 102   // (32+2)*3

// Correctly-rounded sobel: terms (weights +-1, +-2) are exact products.
__device__ __forceinline__ void sobel_at(const float* sb, int bi,
                                         bool ym, bool yp, bool xm, bool xp,
                                         float& gx, float& gy) {
    float v00 = (ym && xm) ? sb[bi - SBW - 3] : 0.f;
    float v01 =  ym        ? sb[bi - SBW]     : 0.f;
    float v02 = (ym && xp) ? sb[bi - SBW + 3] : 0.f;
    float v10 =  xm        ? sb[bi - 3]       : 0.f;
    float v12 =  xp        ? sb[bi + 3]       : 0.f;
    float v20 = (yp && xm) ? sb[bi + SBW - 3] : 0.f;
    float v21 =  yp        ? sb[bi + SBW]     : 0.f;
    float v22 = (yp && xp) ? sb[bi + SBW + 3] : 0.f;
    {
        float tx[6] = { -v00, v02, __fmul_rn(-2.f, v10), __fmul_rn(2.f, v12), -v20, v22 };
        gx = sum_exact<6>(tx);
    }
    {
        float ty[6] = { -v00, __fmul_rn(-2.f, v01), -v02, v20, __fmul_rn(2.f, v21), v22 };
        gy = sum_exact<6>(ty);
    }
}

__device__ __forceinline__ float mag_of(float gx, float gy) {
    float s = __fadd_rn(__fmul_rn(gx, gx), __fmul_rn(gy, gy));
    return __fsqrt_rn(s);
}

__global__ void nms_k() {
    __shared__ float sb[20 * SBW];   // blurred: rows [y0-2, y0+17], cols [x0-2, x0+33] x3ch
    __shared__ float sm[18 * SMW];   // mag:     rows [y0-1, y0+16], cols [x0-1, x0+32] x3ch
    int tid = threadIdx.x;
    int x0 = blockIdx.x * TX;
    int y0 = blockIdx.y * TY;
    int b  = blockIdx.z;
    const float* bl = g_blur + (size_t)b * Hv * Wv * 3;

    for (int i = tid; i < 20 * SBW; i += 256) {
        int r = i / SBW, col = i - r * SBW;
        int lx = col / 3, c = col - lx * 3;
        int gy = (y0 + r - 2) & 511;
        int gx = (x0 + lx - 2) & 511;
        sb[i] = bl[(gy * Wv + gx) * 3 + c];
    }
    __syncthreads();

    for (int i = tid; i < 18 * SMW; i += 256) {
        int r = i / SMW, col = i - r * SMW;
        int lx = col / 3, c = col - lx * 3;
        int ry = (y0 + r - 1) & 511;
        int rx = (x0 + lx - 1) & 511;
        int bi = (r + 1) * SBW + (lx + 1) * 3 + c;
        float gxv, gyv;
        sobel_at(sb, bi, ry > 0, ry < 511, rx > 0, rx < 511, gxv, gyv);
        sm[i] = mag_of(gxv, gyv);
    }
    __syncthreads();

    const float SCALE = (float)(180.0 / 3.14159);
    for (int i = tid; i < TY * TX * 3; i += 256) {
        int c = i / (TY * TX);
        int rem = i - c * (TY * TX);
        int r = rem / TX, lx = rem - r * TX;
        int iy = y0 + r, ix = x0 + lx;
        int bi = (r + 2) * SBW + (lx + 2) * 3 + c;
        float gxv, gyv;
        sobel_at(sb, bi, iy > 0, iy < 511, ix > 0, ix < 511, gxv, gyv);

        // Elementwise exactly as an XLA GPU lowering would: libdevice atan2f,
        // f32 multiply by the f32(180/3.14159) constant, single +180 fixup.
        float ang = __fmul_rn(atan2f(gyv, gxv), SCALE);
        if (ang < 0.f) ang = __fadd_rn(ang, 180.f);

        int mi = (r + 1) * SMW + (lx + 1) * 3 + c;
        float m = sm[mi];
        float na, nb;
        if (ang <= 22.5f || ang > 157.5f) { na = sm[mi + 3];       nb = sm[mi - 3]; }
        else if (ang <= 67.5f)            { na = sm[mi + SMW - 3]; nb = sm[mi - SMW + 3]; }
        else if (ang <= 112.5f)           { na = sm[mi + SMW];     nb = sm[mi - SMW]; }
        else                              { na = sm[mi + SMW + 3]; nb = sm[mi - SMW - 3]; }
        float sup = (m >= na && m >= nb) ? m : 0.f;
        uint8_t cls = sup >= 0.3f ? (uint8_t)2 : (sup >= 0.1f ? (uint8_t)1 : (uint8_t)0);
        g_state[((size_t)(b * 3 + c) * Hv + iy) * Wv + ix] = cls;
    }
}

// ----------------------------------------------------- K3: hysteresis (exact)
__device__ __forceinline__ void gbar(unsigned nb, unsigned& gen) {
    __syncthreads();
    if (threadIdx.x == 0) {
        __threadfence();
        unsigned target = gen + 1;
        if (atomicAdd(&g_cnt, 1u) == nb - 1) {
            g_cnt = 0;
            __threadfence();
            atomicExch(&g_gen, target);
        } else {
            while (atomicAdd(&g_gen, 0u) < target) __nanosleep(100);
            __threadfence();
        }
    }
    gen++;
    __syncthreads();
}

#define NPLANES (Bv * Cv)              // 48
#define NTILES  (NPLANES * 64)         // 8x8 tiles of 64x64 per plane = 3072

__global__ void __launch_bounds__(256) hyst_k(int nblocks) {
    __shared__ uint8_t s[66 * 66];
    __shared__ int s_ch;
    unsigned gen = 0;
    int tid = threadIdx.x;

    for (int outer = 0; outer < 10000; ++outer) {
        int any = 0;
        for (int t = blockIdx.x; t < NTILES; t += nblocks) {
            int plane = t >> 6;
            int ty = (t >> 3) & 7, tx = t & 7;
            uint8_t* pl = g_state + (size_t)plane * Hv * Wv;
            int y0 = ty * 64, x0 = tx * 64;
            // load 66x66 with circular wrap halo
            for (int i = tid; i < 66 * 66; i += 256) {
                int ly = i / 66, lx = i - ly * 66;
                s[i] = pl[(((y0 + ly - 1) & 511) * Wv) + ((x0 + lx - 1) & 511)];
            }
            int tch = 0;
            for (;;) {
                __syncthreads();
                if (tid == 0) s_ch = 0;
                __syncthreads();
                int lc = 0;
                for (int i = tid; i < 4096; i += 256) {
                    int ly = (i >> 6) + 1, lx = (i & 63) + 1;
                    int idx = ly * 66 + lx;
                    if (s[idx] == 1) {
                        int o = s[idx - 67] | s[idx - 66] | s[idx - 65] | s[idx - 1] |
                                s[idx + 1]  | s[idx + 65] | s[idx + 66] | s[idx + 67];
                        if (o & 2) { s[idx] = 2; lc = 1; }
                    }
                }
                if (lc) s_ch = 1;
                __syncthreads();
                if (!s_ch) break;
                tch = 1;
            }
            if (tch) {
                any = 1;
                for (int i = tid; i < 4096; i += 256) {
                    int ly = i >> 6, lx = i & 63;
                    pl[(y0 + ly) * Wv + x0 + lx] = s[(ly + 1) * 66 + lx + 1];
                }
            }
            __syncthreads();
        }
        if (any && tid == 0) atomicExch(&g_changed, 1);
        gbar(nblocks, gen);                              // all flag-sets visible
        if (tid == 0) s_ch = *((volatile int*)&g_changed);
        gbar(nblocks, gen);                              // all blocks have read the flag
        if (tid == 0 && blockIdx.x == 0) g_changed = 0;
        gbar(nblocks, gen);                              // reset visible before next round's sets
        if (!s_ch) break;                                // uniform across grid
    }
}

// ----------------------------------------------------------- K4: write output
__global__ void out_k(float* __restrict__ out) {
    int n = blockIdx.x * 256 + threadIdx.x;
    if (n >= TOT) return;
    int c = n % 3;
    int t = n / 3;
    int xx = t & 511; t >>= 9;
    int y  = t & 511;
    int b  = t >> 9;
    out[n] = (g_state[(((size_t)(b * 3 + c) << 9) + y) * Wv + xx] == 2) ? 1.f : 0.f;
}

// --------------------------------------------------------------- launch
extern "C" void kernel_launch(void* const* d_in, const int* in_sizes, int n_in,
                              void* d_out, int out_size) {
    const float* x = (const float*)d_in[0];
    float* out = (float*)d_out;

    blur_k<<<TOT / 256, 256>>>(x);

    dim3 g2(Wv / TX, Hv / TY, Bv);
    nms_k<<<g2, 256>>>();

    int dev = 0;
    cudaGetDevice(&dev);
    int sm = 148;
    cudaDeviceGetAttribute(&sm, cudaDevAttrMultiProcessorCount, dev);
    if (sm < 1) sm = 1;
    hyst_k<<<sm, 256>>>(sm);   // 1 block/SM -> co-residency guaranteed for grid barrier

    out_k<<<TOT / 256, 256>>>(out);
}

// round 4
// speedup vs baseline: 2.0669x; 2.0669x over previous
#include <cuda_runtime.h>
#include <stdint.h>
#include <math.h>

#define Bv 16
#define Hv 512
#define Wv 512
#define Cv 3
#define TOT (Bv*Hv*Wv*Cv)   // 12,582,912
#define NPLANES (Bv*Cv)     // 48

// Scratch (device globals -- no runtime allocation allowed)
__device__ float    g_mag[TOT];                       // planar [plane][y][x]
__device__ uint8_t  g_sect[TOT];                      // planar, 0..3
__device__ uint32_t g_weakbits[NPLANES * Hv * 16];    // 16 u32 words per row
__device__ uint32_t g_strongbits[NPLANES * Hv * 16];

// ---------------- error-free compensated summation (pure f32, exact products)
__device__ __forceinline__ void two_sum(float a, float b, float& s, float& e) {
    s = __fadd_rn(a, b);
    float bb = __fsub_rn(s, a);
    e = __fadd_rn(__fsub_rn(a, __fsub_rn(s, bb)), __fsub_rn(b, bb));
}

template <int N>
__device__ __forceinline__ float sum_exact(const float* t) {
    float s = t[0], e = 0.f;
#pragma unroll
    for (int i = 1; i < N; ++i) {
        float ei;
        two_sum(s, t[i], s, ei);
        e = __fadd_rn(e, ei);
    }
    return __fadd_rn(s, e);   // correctly-rounded sum (ORO Sum2)
}

// ============================ K1: blur + sobel + mag + sector (fused) ========
#define TY 16
#define TX 32
#define SIW 108   // (32+4)*3  input smem row width (interleaved c)
#define SLW 102   // (32+2)*3  blurred smem row width

__device__ __forceinline__ void sobel_at(const float* sb, int bi,
                                         bool ym, bool yp, bool xm, bool xp,
                                         float& gx, float& gy) {
    float v00 = (ym && xm) ? sb[bi - SLW - 3] : 0.f;
    float v01 =  ym        ? sb[bi - SLW]     : 0.f;
    float v02 = (ym && xp) ? sb[bi - SLW + 3] : 0.f;
    float v10 =  xm        ? sb[bi - 3]       : 0.f;
    float v12 =  xp        ? sb[bi + 3]       : 0.f;
    float v20 = (yp && xm) ? sb[bi + SLW - 3] : 0.f;
    float v21 =  yp        ? sb[bi + SLW]     : 0.f;
    float v22 = (yp && xp) ? sb[bi + SLW + 3] : 0.f;
    {
        float tx[6] = { -v00, v02, __fmul_rn(-2.f, v10), __fmul_rn(2.f, v12), -v20, v22 };
        gx = sum_exact<6>(tx);
    }
    {
        float ty[6] = { -v00, __fmul_rn(-2.f, v01), -v02, v20, __fmul_rn(2.f, v21), v22 };
        gy = sum_exact<6>(ty);
    }
}

__device__ __forceinline__ float mag_of(float gx, float gy) {
    float s = __fadd_rn(__fmul_rn(gx, gx), __fmul_rn(gy, gy));
    return __fsqrt_rn(s);
}

__global__ void __launch_bounds__(256) mag_k(const float* __restrict__ x) {
    __shared__ float si[20 * SIW];   // input: rows y0-2..y0+17, cols x0-2..x0+33, 3ch
    __shared__ float sl[18 * SLW];   // blur:  rows y0-1..y0+16, cols x0-1..x0+32, 3ch
    int tid = threadIdx.x;
    int x0 = blockIdx.x * TX;
    int y0 = blockIdx.y * TY;
    int b  = blockIdx.z;
    const float* base = x + (size_t)b * Hv * Wv * 3;

    // load input with REAL-coordinate zero padding
    for (int i = tid; i < 20 * SIW; i += 256) {
        int r = i / SIW, col = i - r * SIW;
        int lx = col / 3, c = col - lx * 3;
        int gy = y0 + r - 2;
        int gx = x0 + lx - 2;
        bool ok = ((unsigned)gy < (unsigned)Hv) && ((unsigned)gx < (unsigned)Wv);
        si[i] = ok ? __ldg(base + (gy * Wv + gx) * 3 + c) : 0.f;
    }
    __syncthreads();

    // blur (correctly rounded; products with power-of-two weights exact)
    for (int i = tid; i < 18 * SLW; i += 256) {
        int r = i / SLW, col = i - r * SLW;
        int lx = col / 3, c = col - lx * 3;
        int ii = (r + 1) * SIW + (lx + 1) * 3 + c;   // centered on input smem
        float t[9];
        int k = 0;
#pragma unroll
        for (int dy = -1; dy <= 1; ++dy) {
#pragma unroll
            for (int dx = -1; dx <= 1; ++dx) {
                float w = (dy == 0) ? ((dx == 0) ? 0.25f : 0.125f)
                                    : ((dx == 0) ? 0.125f : 0.0625f);
                t[k++] = __fmul_rn(si[ii + dy * SIW + dx * 3], w);
            }
        }
        sl[i] = sum_exact<9>(t);
    }
    __syncthreads();

    const float SCALE = (float)(180.0 / 3.14159);
    for (int i = tid; i < TY * TX * 3; i += 256) {
        int c = i / (TY * TX);
        int rem = i - c * (TY * TX);
        int r = rem / TX, lx = rem - r * TX;
        int iy = y0 + r, ix = x0 + lx;
        int bi = (r + 1) * SLW + (lx + 1) * 3 + c;
        float gxv, gyv;
        sobel_at(sl, bi, iy > 0, iy < 511, ix > 0, ix < 511, gxv, gyv);
        float m = mag_of(gxv, gyv);

        float ang = __fmul_rn(atan2f(gyv, gxv), SCALE);
        if (ang < 0.f) ang = __fadd_rn(ang, 180.f);
        uint8_t sct;
        if (ang <= 22.5f || ang > 157.5f) sct = 0;
        else if (ang <= 67.5f)            sct = 1;
        else if (ang <= 112.5f)           sct = 2;
        else                              sct = 3;

        size_t o = ((size_t)(b * 3 + c) * Hv + iy) * Wv + ix;
        g_mag[o] = m;
        g_sect[o] = sct;
    }
}

// ============================ K2: NMS + threshold -> bit-packed planes =======
#define K2R 16              // inner rows per block
#define K2W 516             // 514 used (x=-1..512 wrapped), padded

__global__ void __launch_bounds__(256) nms2_k() {
    __shared__ float sm[(K2R + 2) * K2W];
    int tid = threadIdx.x;
    int y0 = blockIdx.x * K2R;
    int plane = blockIdx.y;
    const float* mg = g_mag + (size_t)plane * Hv * Wv;
    const uint8_t* sc = g_sect + (size_t)plane * Hv * Wv;

    for (int i = tid; i < (K2R + 2) * 514; i += 256) {
        int r = i / 514, col = i - r * 514;
        int gy = (y0 + r - 1) & 511;
        int gx = (col - 1) & 511;
        sm[r * K2W + col] = mg[gy * Wv + gx];
    }
    __syncthreads();

    uint32_t lane = tid & 31;
#pragma unroll 4
    for (int k = 0; k < 32; ++k) {
        int p = k * 256 + tid;            // 0..8191 over 16 rows x 512 cols
        int row = p >> 9;
        int xx = p & 511;
        int mi = (row + 1) * K2W + (xx + 1);
        float m = sm[mi];
        uint8_t s = sc[(y0 + row) * Wv + xx];
        float na, nb;
        if (s == 0)      { na = sm[mi + 1];       nb = sm[mi - 1]; }
        else if (s == 1) { na = sm[mi + K2W - 1]; nb = sm[mi - K2W + 1]; }
        else if (s == 2) { na = sm[mi + K2W];     nb = sm[mi - K2W]; }
        else             { na = sm[mi + K2W + 1]; nb = sm[mi - K2W - 1]; }
        float sup = (m >= na && m >= nb) ? m : 0.f;
        bool strong = sup >= 0.3f;
        bool weak   = (sup >= 0.1f) && !strong;
        uint32_t wbal = __ballot_sync(0xFFFFFFFFu, weak);
        uint32_t sbal = __ballot_sync(0xFFFFFFFFu, strong);
        if (lane == 0) {
            int idx = ((plane << 9) + y0 + row) * 16 + (xx >> 5);
            g_weakbits[idx] = wbal;
            g_strongbits[idx] = sbal;
        }
    }
}

// ============================ K3: hysteresis on bitboards ====================
__device__ __forceinline__ void hexpand8(const uint64_t* S, uint64_t* E) {
#pragma unroll
    for (int j = 0; j < 8; ++j) {
        uint64_t s = S[j];
        uint64_t l = (s << 1) | (S[(j + 7) & 7] >> 63);   // neighbor x-1
        uint64_t r = (s >> 1) | (S[(j + 1) & 7] << 63);   // neighbor x+1
        E[j] = s | l | r;
    }
}

// row-local closure: promote weak bits connected horizontally to strong
__device__ __forceinline__ void row_closure(uint64_t* S, const uint64_t* W) {
    for (;;) {
        uint64_t E[8];
        hexpand8(S, E);
        uint64_t any = 0;
#pragma unroll
        for (int j = 0; j < 8; ++j) {
            uint64_t n = W[j] & E[j] & ~S[j];
            any |= n;
            S[j] |= n;
        }
        if (!any) break;
    }
}

__global__ void __launch_bounds__(512) hyst_k() {
    __shared__ uint64_t H[512][8];
    int row = threadIdx.x;          // one row per thread
    int plane = blockIdx.x;
    int base = ((plane << 9) + row) * 16;

    uint64_t S[8], W[8];
#pragma unroll
    for (int j = 0; j < 8; ++j) {
        S[j] = (uint64_t)g_strongbits[base + 2 * j] |
               ((uint64_t)g_strongbits[base + 2 * j + 1] << 32);
        W[j] = (uint64_t)g_weakbits[base + 2 * j] |
               ((uint64_t)g_weakbits[base + 2 * j + 1] << 32);
    }
    row_closure(S, W);

    int up = (row + 511) & 511;
    int dn = (row + 1) & 511;

    for (;;) {
        uint64_t E[8];
        hexpand8(S, E);
#pragma unroll
        for (int j = 0; j < 8; ++j) H[row][j] = E[j];
        __syncthreads();
        uint64_t any = 0;
#pragma unroll
        for (int j = 0; j < 8; ++j) {
            uint64_t n = W[j] & (H[up][j] | H[dn][j]) & ~S[j];
            any |= n;
            S[j] |= n;
        }
        if (any) row_closure(S, W);
        if (!__syncthreads_or(any != 0)) break;
    }

#pragma unroll
    for (int j = 0; j < 8; ++j) {
        g_strongbits[base + 2 * j]     = (uint32_t)S[j];
        g_strongbits[base + 2 * j + 1] = (uint32_t)(S[j] >> 32);
    }
}

// ============================ K4: expand strong bits -> f32 NHWC =============
__global__ void out_k(float* __restrict__ out) {
    int n = blockIdx.x * 256 + threadIdx.x;
    if (n >= TOT) return;
    int c = n % 3;
    int t = n / 3;
    int xx = t & 511;
    int y  = (t >> 9) & 511;
    int b  = t >> 18;
    uint32_t w = g_strongbits[(((b * 3 + c) << 9) + y) * 16 + (xx >> 5)];
    out[n] = ((w >> (xx & 31)) & 1u) ? 1.f : 0.f;
}

// --------------------------------------------------------------- launch
extern "C" void kernel_launch(void* const* d_in, const int* in_sizes, int n_in,
                              void* d_out, int out_size) {
    const float* x = (const float*)d_in[0];
    float* out = (float*)d_out;

    dim3 g1(Wv / TX, Hv / TY, Bv);
    mag_k<<<g1, 256>>>(x);

    dim3 g2(Hv / K2R, NPLANES);
    nms2_k<<<g2, 256>>>();

    hyst_k<<<NPLANES, 512>>>();

    out_k<<<TOT / 256, 256>>>(out);
}